// round 13
// baseline (speedup 1.0000x reference)
#include <cuda_runtime.h>
#include <math.h>

#define BB 64
#define SS 4
#define LL 64
#define CC 32
#define HH 4
#define DD 8
#define CPD 16
#define LN_EPS 1e-5f

__device__ float g_xbuf[BB * LL * SS * CC];   // (b,l,s,c) after row attention
__device__ float g_m[BB * LL * CC];           // (b,l,c) track-mean
__device__ float g_we[96];                    // Win · ew  per row
__device__ float g_wcR[96 * 64];              // [r][i] = Win_r·(eb+pos_i)+b_r
__device__ float g_wcT[64 * 96];              // token-major [i][r]

// SiLU via tanh.approx: x*sigmoid(x) = h*tanh(h)+h with h=x/2 (1 MUFU, 3 issues)
__device__ __forceinline__ float silu(float x) {
    float h = 0.5f * x, t;
    asm("tanh.approx.f32 %0, %1;" : "=f"(t) : "f"(h));
    return fmaf(h, t, h);
}

// ---------------------------------------------------------------------------
// k_pre: position-constant projection tables (row attention is rank-1 in data)
// ---------------------------------------------------------------------------
__global__ __launch_bounds__(64)
void k_pre(const float* __restrict__ Win, const float* __restrict__ bin,
           const float* __restrict__ eb,  const float* __restrict__ pos,
           const float* __restrict__ ew)
{
    const int r = blockIdx.x;
    const int i = threadIdx.x;
    float a = bin[r];
    #pragma unroll
    for (int c = 0; c < CC; c++)
        a += Win[r * CC + c] * (eb[c] + pos[i * CC + c]);
    g_wcR[r * 64 + i] = a;
    g_wcT[i * 96 + r] = a;
    if (i == 0) {
        float e = 0.f;
        #pragma unroll
        for (int c = 0; c < CC; c++) e += Win[r * CC + c] * ew[c];
        g_we[r] = e;
    }
}

// ---------------------------------------------------------------------------
// Kernel 1: row MHA + residual LN.  grid = B*S*2 = 512, single wave (256,4).
// ---------------------------------------------------------------------------
__global__ __launch_bounds__(256, 4)
void k_row_attn(const float* __restrict__ ctcf, const float* __restrict__ hac,
                const float* __restrict__ me1,  const float* __restrict__ me3,
                const float* __restrict__ ew,   const float* __restrict__ eb,
                const float* __restrict__ pos,
                const float* __restrict__ Wout, const float* __restrict__ bout,
                const float* __restrict__ lng,  const float* __restrict__ lnb)
{
    __shared__ __align__(16) float sk[LL * 36];
    __shared__ __align__(16) float sv[LL * 36];
    __shared__ float so[32 * 33];
    __shared__ float spos[32 * 33];
    __shared__ float sWout[CC * CC];
    __shared__ float pacc[HH][32][9];
    __shared__ float pmu[8][32], pvar[8][32];
    __shared__ float ssval[LL];
    __shared__ float sbo[CC], sg[CC], sb2[CC], sew[CC], seb[CC];

    const int blk = blockIdx.x;
    const int b = blk >> 3;
    const int s = (blk >> 1) & 3;
    const int ihalf = blk & 1;
    const int tid = threadIdx.x;
    const int w = tid >> 5;
    const int lane = tid & 31;
    const int h = w & 3;
    const int jh = w >> 2;
    const int i = ihalf * 32 + lane;

    const float* sig = (s == 0) ? ctcf : (s == 1) ? hac : (s == 2) ? me1 : me3;
    if (tid < 64) ssval[tid] = sig[b * LL + tid];
    for (int t = tid; t < CC * CC; t += 256) sWout[t] = Wout[t];
    if (tid < CC) {
        sbo[tid] = bout[tid]; sg[tid] = lng[tid]; sb2[tid] = lnb[tid];
        sew[tid] = ew[tid];  seb[tid] = eb[tid];
    }
    for (int t = tid; t < 1024; t += 256)
        spos[(t >> 5) * 33 + (t & 31)] = pos[ihalf * 1024 + t];
    __syncthreads();

    for (int t = tid; t < 2048; t += 256) {
        const int j = t >> 5, d = t & 31;
        const float sj = ssval[j];
        sk[j * 36 + d] = sj * g_we[32 + d] + g_wcT[j * 96 + 32 + d];
        sv[j * 36 + d] = sj * g_we[64 + d] + g_wcT[j * 96 + 64 + d];
    }
    const float sval_i = ssval[i];
    float q[DD];
    #pragma unroll
    for (int d = 0; d < DD; d++)
        q[d] = sval_i * g_we[h * DD + d] + g_wcR[(h * DD + d) * 64 + i];
    __syncthreads();

    const float scale = 0.3535533905932738f;
    float se = 0.f;
    float acc[DD];
    #pragma unroll
    for (int d = 0; d < DD; d++) acc[d] = 0.f;
    const int j0 = jh * 32;
    #pragma unroll 4
    for (int jj = 0; jj < 32; jj++) {
        const int j = j0 + jj;
        float4 k0 = *(const float4*)&sk[j * 36 + h * DD];
        float4 k1 = *(const float4*)&sk[j * 36 + h * DD + 4];
        float a = q[0]*k0.x + q[1]*k0.y + q[2]*k0.z + q[3]*k0.w
                + q[4]*k1.x + q[5]*k1.y + q[6]*k1.z + q[7]*k1.w;
        float p = __expf(a * scale);
        se += p;
        float4 v0 = *(const float4*)&sv[j * 36 + h * DD];
        float4 v1 = *(const float4*)&sv[j * 36 + h * DD + 4];
        acc[0] += p * v0.x; acc[1] += p * v0.y; acc[2] += p * v0.z; acc[3] += p * v0.w;
        acc[4] += p * v1.x; acc[5] += p * v1.y; acc[6] += p * v1.z; acc[7] += p * v1.w;
    }
    if (jh == 1) {
        #pragma unroll
        for (int d = 0; d < DD; d++) pacc[h][lane][d] = acc[d];
        pacc[h][lane][8] = se;
    }
    __syncthreads();
    if (jh == 0) {
        se += pacc[h][lane][8];
        #pragma unroll
        for (int d = 0; d < DD; d++) acc[d] += pacc[h][lane][d];
        const float inv = __fdividef(1.f, se);
        #pragma unroll
        for (int d = 0; d < DD; d++) so[lane * 33 + h * DD + d] = acc[d] * inv;
    }
    __syncthreads();

    float orow[CC];
    #pragma unroll
    for (int k = 0; k < CC; k++) orow[k] = so[lane * 33 + k];
    const int cb = h * DD + jh * 4;
    float y[4];
    float part = 0.f;
    #pragma unroll
    for (int cc = 0; cc < 4; cc++) {
        const int c = cb + cc;
        float a = sbo[c];
        #pragma unroll
        for (int k = 0; k < CC; k++) a += orow[k] * sWout[c * CC + k];
        const float x = sval_i * sew[c] + seb[c] + spos[lane * 33 + c];
        y[cc] = a + x;
        part += y[cc];
    }
    pmu[w][lane] = part;
    __syncthreads();
    float mu = 0.f;
    #pragma unroll
    for (int t = 0; t < 8; t++) mu += pmu[t][lane];
    mu *= (1.f / CC);
    float vp = 0.f;
    #pragma unroll
    for (int cc = 0; cc < 4; cc++) { float d = y[cc] - mu; vp += d * d; }
    pvar[w][lane] = vp;
    __syncthreads();
    float var = 0.f;
    #pragma unroll
    for (int t = 0; t < 8; t++) var += pvar[t][lane];
    var *= (1.f / CC);
    const float rs = rsqrtf(var + LN_EPS);

    float4 o4;
    o4.x = (y[0] - mu) * rs * sg[cb + 0] + sb2[cb + 0];
    o4.y = (y[1] - mu) * rs * sg[cb + 1] + sb2[cb + 1];
    o4.z = (y[2] - mu) * rs * sg[cb + 2] + sb2[cb + 2];
    o4.w = (y[3] - mu) * rs * sg[cb + 3] + sb2[cb + 3];
    *(float4*)&g_xbuf[((b * LL + i) * SS + s) * CC + cb] = o4;
}

// ---------------------------------------------------------------------------
// Kernel 2: column MHA (seq=4) + LN + mean over S.  grid = B*8 = 512, (256,4).
// ---------------------------------------------------------------------------
__global__ __launch_bounds__(256, 4)
void k_col_attn(const float* __restrict__ Win,  const float* __restrict__ bin,
                const float* __restrict__ Wout, const float* __restrict__ bout,
                const float* __restrict__ lng,  const float* __restrict__ lnb)
{
    __shared__ float sx[32 * 33];
    __shared__ float sk[32 * 33];
    __shared__ float sv[32 * 33];
    __shared__ float so[32 * 33];
    __shared__ float sWin[96 * CC];
    __shared__ float sWout[CC * CC];
    __shared__ float sbin[96];
    __shared__ float sbo[CC], sg[CC], sb2[CC];
    __shared__ float pmu[8][32], pvar[8][32];

    const int blk = blockIdx.x;
    const int b = blk >> 3;
    const int lg = blk & 7;
    const int tid = threadIdx.x;
    const int w = tid >> 5;
    const int tk = tid & 31;
    const int h = w & 3;
    const int sp = w >> 2;

    const int gb = (b * 64 + lg * 8) * SS * CC;
    for (int t = tid; t < 1024; t += 256)
        sx[(t >> 5) * 33 + (t & 31)] = g_xbuf[gb + t];
    for (int t = tid; t < 96 * CC; t += 256) sWin[t] = Win[t];
    for (int t = tid; t < CC * CC; t += 256) sWout[t] = Wout[t];
    if (tid < 96) sbin[tid] = bin[tid];
    if (tid < CC) { sbo[tid] = bout[tid]; sg[tid] = lng[tid]; sb2[tid] = lnb[tid]; }
    __syncthreads();

    float xr[CC];
    #pragma unroll
    for (int c = 0; c < CC; c++) xr[c] = sx[tk * 33 + c];

    float q[DD];
    if (sp == 0) {
        #pragma unroll
        for (int d = 0; d < DD; d++) {
            const int r = h * DD + d;
            float a = sbin[r];
            #pragma unroll
            for (int c = 0; c < CC; c++) a += xr[c] * sWin[r * CC + c];
            q[d] = a;
        }
    } else {
        #pragma unroll
        for (int d = 0; d < DD; d++) {
            const int r = CC + h * DD + d;
            float a = sbin[r];
            #pragma unroll
            for (int c = 0; c < CC; c++) a += xr[c] * sWin[r * CC + c];
            sk[tk * 33 + h * DD + d] = a;
        }
        #pragma unroll
        for (int d = 0; d < DD; d++) {
            const int r = 2 * CC + h * DD + d;
            float a = sbin[r];
            #pragma unroll
            for (int c = 0; c < CC; c++) a += xr[c] * sWin[r * CC + c];
            sv[tk * 33 + h * DD + d] = a;
        }
    }
    __syncthreads();

    if (sp == 0) {
        const float scale = 0.3535533905932738f;
        const int base = tk & ~3;
        float se = 0.f;
        float acc[DD];
        #pragma unroll
        for (int d = 0; d < DD; d++) acc[d] = 0.f;
        #pragma unroll
        for (int j = 0; j < SS; j++) {
            float a = 0.f;
            #pragma unroll
            for (int d = 0; d < DD; d++) a += q[d] * sk[(base + j) * 33 + h * DD + d];
            float p = __expf(a * scale);
            se += p;
            #pragma unroll
            for (int d = 0; d < DD; d++) acc[d] += p * sv[(base + j) * 33 + h * DD + d];
        }
        const float inv = __fdividef(1.f, se);
        #pragma unroll
        for (int d = 0; d < DD; d++) so[tk * 33 + h * DD + d] = acc[d] * inv;
    }
    __syncthreads();

    float orow[CC];
    #pragma unroll
    for (int k = 0; k < CC; k++) orow[k] = so[tk * 33 + k];
    const int cb = h * DD + sp * 4;
    float y[4];
    float part = 0.f;
    #pragma unroll
    for (int cc = 0; cc < 4; cc++) {
        const int c = cb + cc;
        float a = sbo[c];
        #pragma unroll
        for (int k = 0; k < CC; k++) a += orow[k] * sWout[c * CC + k];
        y[cc] = a + sx[tk * 33 + c];
        part += y[cc];
    }
    pmu[w][tk] = part;
    __syncthreads();
    float mu = 0.f;
    #pragma unroll
    for (int t = 0; t < 8; t++) mu += pmu[t][tk];
    mu *= (1.f / CC);
    float vp = 0.f;
    #pragma unroll
    for (int cc = 0; cc < 4; cc++) { float d = y[cc] - mu; vp += d * d; }
    pvar[w][tk] = vp;
    __syncthreads();
    float var = 0.f;
    #pragma unroll
    for (int t = 0; t < 8; t++) var += pvar[t][tk];
    var *= (1.f / CC);
    const float rs = rsqrtf(var + LN_EPS);

    float m0[4];
    #pragma unroll
    for (int cc = 0; cc < 4; cc++) {
        float v = (y[cc] - mu) * rs * sg[cb + cc] + sb2[cb + cc];
        v += __shfl_xor_sync(0xffffffffu, v, 1);
        v += __shfl_xor_sync(0xffffffffu, v, 2);
        m0[cc] = v * 0.25f;
    }
    if ((tk & 3) == 0) {
        const int l = lg * 8 + (tk >> 2);
        *(float4*)&g_m[(b * LL + l) * CC + cb] = make_float4(m0[0], m0[1], m0[2], m0[3]);
    }
}

// ---------------------------------------------------------------------------
// Kernel 3: grid = B*8 = 512 (8 i's/block), block = 256.
// Phase 1: u GEMM (register-tiled, Wp L1-hot).
// Phase 2: PARALLEL 2-j outputs (best LDS amortization, proven R9), with
//          __launch_bounds__(256,5): 51-reg target -> 5 blocks/SM, 40 warps.
//          (R12 showed ptxas uses exactly the declared budget; the parallel
//          form needs ~48-50 regs so it should fit with minimal spill.)
// ---------------------------------------------------------------------------
__global__ __launch_bounds__(256, 5)
void k_pair(const float* __restrict__ Wp, const float* __restrict__ bp,
            const float* __restrict__ png, const float* __restrict__ pnb,
            float* __restrict__ out)
{
    __shared__ __align__(16) float sm[LL * 36];
    __shared__ __align__(16) float su[8 * 512];
    __shared__ float snrm[LL];
    __shared__ float sbp[CPD], sg[CPD], sb[CPD];

    const int b  = blockIdx.x >> 3;
    const int ch = blockIdx.x & 7;
    const int tid = threadIdx.x;
    const int ib = ch * 8;

    for (int t = tid; t < LL * CC; t += 256)
        sm[(t >> 5) * 36 + (t & 31)] = g_m[b * (LL * CC) + t];
    if (tid < CPD) { sbp[tid] = bp[tid]; sg[tid] = png[tid]; sb[tid] = pnb[tid]; }
    __syncthreads();

    if (tid < LL) {
        float a = 0.f;
        #pragma unroll
        for (int c = 0; c < CC; c++) { float v = sm[tid * 36 + c]; a += v * v; }
        snrm[tid] = sqrtf(a);
    }

    // phase 1: u for 8 i's. thread -> (p0, c2) and (p0+8, c2).
    {
        const int p0 = tid >> 5;           // 0..7 (warp-uniform)
        const int c2 = tid & 31;
        float a0[8], a1[8];
        #pragma unroll
        for (int il = 0; il < 8; il++) { a0[il] = 0.f; a1[il] = 0.f; }
        #pragma unroll 8
        for (int c1 = 0; c1 < CC; c1++) {
            const float w0 = Wp[p0 * 1024 + c1 * CC + c2];
            const float w1 = Wp[(p0 + 8) * 1024 + c1 * CC + c2];
            #pragma unroll
            for (int il = 0; il < 8; il++) {
                const float mv = sm[(ib + il) * 36 + c1];   // uniform broadcast
                a0[il] += mv * w0;
                a1[il] += mv * w1;
            }
        }
        #pragma unroll
        for (int il = 0; il < 8; il++) {
            su[il * 512 + p0 * CC + c2]       = a0[il];
            su[il * 512 + (p0 + 8) * CC + c2] = a1[il];
        }
    }
    __syncthreads();

    // phase 2: thread = (il, jl); outputs (i, jl) and (i, jl+32) in parallel
    const int il = tid >> 5;           // 0..7 (warp-uniform)
    const int jl = tid & 31;
    const int i  = ib + il;
    const int ja = jl, jb = jl + 32;

    float fa[CPD], fb[CPD];
    #pragma unroll
    for (int p = 0; p < CPD; p++) { fa[p] = 0.f; fb[p] = 0.f; }

    #pragma unroll
    for (int c4 = 0; c4 < 8; c4++) {
        const float4 ma = *(const float4*)&sm[ja * 36 + c4 * 4];  // conflict-free
        const float4 mb = *(const float4*)&sm[jb * 36 + c4 * 4];
        #pragma unroll
        for (int p = 0; p < CPD; p++) {
            const float4 u4 = *(const float4*)&su[il * 512 + p * CC + c4 * 4]; // broadcast
            fa[p] += u4.x * ma.x + u4.y * ma.y + u4.z * ma.z + u4.w * ma.w;
            fb[p] += u4.x * mb.x + u4.y * mb.y + u4.z * mb.z + u4.w * mb.w;
        }
    }

    const float ni = snrm[i];
    const float inva = __fdividef(1.f, fmaxf(ni * snrm[ja], 1e-6f));
    const float invb = __fdividef(1.f, fmaxf(ni * snrm[jb], 1e-6f));

    float mua = 0.f, mub = 0.f;
    #pragma unroll
    for (int p = 0; p < CPD; p++) {
        fa[p] = fa[p] * inva + sbp[p];
        fb[p] = fb[p] * invb + sbp[p];
        mua += fa[p];
        mub += fb[p];
    }
    mua *= (1.f / CPD); mub *= (1.f / CPD);
    float va = 0.f, vb = 0.f;
    #pragma unroll
    for (int p = 0; p < CPD; p++) {
        float da = fa[p] - mua; va += da * da;
        float db = fb[p] - mub; vb += db * db;
    }
    const float rsa = rsqrtf(va * (1.f / CPD) + LN_EPS);
    const float rsb = rsqrtf(vb * (1.f / CPD) + LN_EPS);
    #pragma unroll
    for (int p = 0; p < CPD; p++) {
        const int obase = ((b * CPD + p) * LL + i) * LL;
        float xa = (fa[p] - mua) * rsa * sg[p] + sb[p];
        float xb = (fb[p] - mub) * rsb * sg[p] + sb[p];
        out[obase + ja] = silu(xa);
        out[obase + jb] = silu(xb);
    }
}

// ---------------------------------------------------------------------------
extern "C" void kernel_launch(void* const* d_in, const int* in_sizes, int n_in,
                              void* d_out, int out_size)
{
    const float* ctcf = (const float*)d_in[0];
    const float* hac  = (const float*)d_in[1];
    const float* me1  = (const float*)d_in[2];
    const float* me3  = (const float*)d_in[3];
    const float* ew   = (const float*)d_in[4];
    const float* eb   = (const float*)d_in[5];
    const float* pos  = (const float*)d_in[6];
    const float* riw  = (const float*)d_in[7];
    const float* rib  = (const float*)d_in[8];
    const float* row_ = (const float*)d_in[9];
    const float* rob  = (const float*)d_in[10];
    const float* rlg  = (const float*)d_in[11];
    const float* rlb  = (const float*)d_in[12];
    const float* ciw  = (const float*)d_in[13];
    const float* cib  = (const float*)d_in[14];
    const float* cow  = (const float*)d_in[15];
    const float* cob  = (const float*)d_in[16];
    const float* clg  = (const float*)d_in[17];
    const float* clb  = (const float*)d_in[18];
    const float* pw   = (const float*)d_in[19];
    const float* pb   = (const float*)d_in[20];
    const float* plg  = (const float*)d_in[21];
    const float* plb  = (const float*)d_in[22];
    float* out = (float*)d_out;

    k_pre<<<96, 64>>>(riw, rib, eb, pos, ew);
    k_row_attn<<<BB * SS * 2, 256>>>(ctcf, hac, me1, me3, ew, eb, pos,
                                     row_, rob, rlg, rlb);
    k_col_attn<<<BB * 8, 256>>>(ciw, cib, cow, cob, clg, clb);
    k_pair<<<BB * 8, 256>>>(pw, pb, plg, plb, out);
}

// round 14
// speedup vs baseline: 1.0332x; 1.0332x over previous
#include <cuda_runtime.h>
#include <math.h>

#define BB 64
#define SS 4
#define LL 64
#define CC 32
#define HH 4
#define DD 8
#define CPD 16
#define LN_EPS 1e-5f

__device__ float g_xbuf[BB * LL * SS * CC];   // (b,l,s,c) after row attention
__device__ float g_m[BB * LL * CC];           // (b,l,c) track-mean
__device__ float g_we[96];                    // Win · ew  per row
__device__ float g_wcR[96 * 64];              // [r][i] = Win_r·(eb+pos_i)+b_r
__device__ float g_wcT[64 * 96];              // token-major [i][r]
// logit decomposition tables (all position-constant):
__device__ float g_A[HH];                     // we_q^h · we_k^h
__device__ float g_Bt[HH * 64];               // [h][j] = we_q^h · c_j^h(k)
__device__ float g_Ct[HH * 64];               // [h][i] = we_k^h · c_i^h(q)
__device__ float g_D[HH * 64 * 64];           // [h][j][i] = c_i^h(q)·c_j^h(k)

// SiLU via tanh.approx: x*sigmoid(x) = h*tanh(h)+h with h=x/2 (1 MUFU, 3 issues)
__device__ __forceinline__ float silu(float x) {
    float h = 0.5f * x, t;
    asm("tanh.approx.f32 %0, %1;" : "=f"(t) : "f"(h));
    return fmaf(h, t, h);
}

// ---------------------------------------------------------------------------
// k_pre: position-constant projection tables (row attention is rank-1 in data)
// ---------------------------------------------------------------------------
__global__ __launch_bounds__(64)
void k_pre(const float* __restrict__ Win, const float* __restrict__ bin,
           const float* __restrict__ eb,  const float* __restrict__ pos,
           const float* __restrict__ ew)
{
    const int r = blockIdx.x;
    const int i = threadIdx.x;
    float a = bin[r];
    #pragma unroll
    for (int c = 0; c < CC; c++)
        a += Win[r * CC + c] * (eb[c] + pos[i * CC + c]);
    g_wcR[r * 64 + i] = a;
    g_wcT[i * 96 + r] = a;
    if (i == 0) {
        float e = 0.f;
        #pragma unroll
        for (int c = 0; c < CC; c++) e += Win[r * CC + c] * ew[c];
        g_we[r] = e;
    }
}

// ---------------------------------------------------------------------------
// k_pre2: logit-decomposition tables from k_pre outputs.
// grid = 4h*64j = 256 blocks, 64 threads (i).
//   D[h][j][i] = sum_d wcR[(h8+d)][i] * wcR[(32+h8+d)][j]
//   B[h][j]    = sum_d we[h8+d]      * wcR[(32+h8+d)][j]
//   C[h][i]    = sum_d we[32+h8+d]   * wcR[(h8+d)][i]
//   A[h]       = sum_d we[h8+d]      * we[32+h8+d]
// ---------------------------------------------------------------------------
__global__ __launch_bounds__(64)
void k_pre2()
{
    const int blk = blockIdx.x;
    const int h = blk >> 6;
    const int j = blk & 63;
    const int i = threadIdx.x;

    float d_acc = 0.f, c_acc = 0.f;
    #pragma unroll
    for (int d = 0; d < DD; d++) {
        const float qc_i = g_wcR[(h * DD + d) * 64 + i];
        const float kc_j = g_wcR[(32 + h * DD + d) * 64 + j];
        d_acc += qc_i * kc_j;
        c_acc += g_we[32 + h * DD + d] * qc_i;
    }
    g_D[(h * 64 + j) * 64 + i] = d_acc;
    if (j == 0) g_Ct[h * 64 + i] = c_acc;
    if (i == 0) {
        float b_acc = 0.f, a_acc = 0.f;
        #pragma unroll
        for (int d = 0; d < DD; d++) {
            b_acc += g_we[h * DD + d] * g_wcR[(32 + h * DD + d) * 64 + j];
            a_acc += g_we[h * DD + d] * g_we[32 + h * DD + d];
        }
        g_Bt[h * 64 + j] = b_acc;
        if (j == 0) g_A[h] = a_acc;
    }
}

// ---------------------------------------------------------------------------
// Kernel 1: row MHA + residual LN via decomposed logits.
// grid = B*S*2 = 512, single wave (256,4).
// logit(i,j) = s_j*F_i + s_i*B[j] + D[i][j],  F_i = s_i*A + C[i].
// No k projection, no sk array, no q registers.
// ---------------------------------------------------------------------------
__global__ __launch_bounds__(256, 4)
void k_row_attn(const float* __restrict__ ctcf, const float* __restrict__ hac,
                const float* __restrict__ me1,  const float* __restrict__ me3,
                const float* __restrict__ ew,   const float* __restrict__ eb,
                const float* __restrict__ pos,
                const float* __restrict__ Wout, const float* __restrict__ bout,
                const float* __restrict__ lng,  const float* __restrict__ lnb)
{
    __shared__ __align__(16) float sv[LL * 36];
    __shared__ float so[32 * 33];
    __shared__ float spos[32 * 33];
    __shared__ float sWout[CC * CC];
    __shared__ float sB[HH * 64];
    __shared__ float pacc[HH][32][9];
    __shared__ float pmu[8][32], pvar[8][32];
    __shared__ float ssval[LL];
    __shared__ float sbo[CC], sg[CC], sb2[CC], sew[CC], seb[CC];

    const int blk = blockIdx.x;
    const int b = blk >> 3;
    const int s = (blk >> 1) & 3;
    const int ihalf = blk & 1;
    const int tid = threadIdx.x;
    const int w = tid >> 5;
    const int lane = tid & 31;
    const int h = w & 3;
    const int jh = w >> 2;
    const int i = ihalf * 32 + lane;

    const float* sig = (s == 0) ? ctcf : (s == 1) ? hac : (s == 2) ? me1 : me3;
    if (tid < 64) ssval[tid] = sig[b * LL + tid];
    for (int t = tid; t < CC * CC; t += 256) sWout[t] = Wout[t];
    if (tid < CC) {
        sbo[tid] = bout[tid]; sg[tid] = lng[tid]; sb2[tid] = lnb[tid];
        sew[tid] = ew[tid];  seb[tid] = eb[tid];
    }
    for (int t = tid; t < 1024; t += 256)
        spos[(t >> 5) * 33 + (t & 31)] = pos[ihalf * 1024 + t];
    if (tid < HH * 64) sB[tid] = g_Bt[tid];
    __syncthreads();

    // fill v only (k eliminated by logit decomposition)
    for (int t = tid; t < 2048; t += 256) {
        const int j = t >> 5, d = t & 31;
        sv[j * 36 + d] = ssval[j] * g_we[64 + d] + g_wcT[j * 96 + 64 + d];
    }
    const float sval_i = ssval[i];
    const float F = sval_i * g_A[h] + g_Ct[h * 64 + i];
    __syncthreads();

    const float scale = 0.3535533905932738f;
    float se = 0.f;
    float acc[DD];
    #pragma unroll
    for (int d = 0; d < DD; d++) acc[d] = 0.f;
    const int j0 = jh * 32;
    const float* Drow = &g_D[(h * 64 + j0) * 64 + i];   // stride 64 per j
    #pragma unroll 4
    for (int jj = 0; jj < 32; jj++) {
        const int j = j0 + jj;
        const float sj = ssval[j];                       // uniform broadcast
        const float Dv = Drow[jj * 64];                  // coalesced LDG, L1-hot
        const float a = fmaf(sj, F, fmaf(sval_i, sB[h * 64 + j], Dv));
        const float p = __expf(a * scale);
        se += p;
        float4 v0 = *(const float4*)&sv[j * 36 + h * DD];
        float4 v1 = *(const float4*)&sv[j * 36 + h * DD + 4];
        acc[0] += p * v0.x; acc[1] += p * v0.y; acc[2] += p * v0.z; acc[3] += p * v0.w;
        acc[4] += p * v1.x; acc[5] += p * v1.y; acc[6] += p * v1.z; acc[7] += p * v1.w;
    }
    if (jh == 1) {
        #pragma unroll
        for (int d = 0; d < DD; d++) pacc[h][lane][d] = acc[d];
        pacc[h][lane][8] = se;
    }
    __syncthreads();
    if (jh == 0) {
        se += pacc[h][lane][8];
        #pragma unroll
        for (int d = 0; d < DD; d++) acc[d] += pacc[h][lane][d];
        const float inv = __fdividef(1.f, se);
        #pragma unroll
        for (int d = 0; d < DD; d++) so[lane * 33 + h * DD + d] = acc[d] * inv;
    }
    __syncthreads();

    float orow[CC];
    #pragma unroll
    for (int k = 0; k < CC; k++) orow[k] = so[lane * 33 + k];
    const int cb = h * DD + jh * 4;
    float y[4];
    float part = 0.f;
    #pragma unroll
    for (int cc = 0; cc < 4; cc++) {
        const int c = cb + cc;
        float a = sbo[c];
        #pragma unroll
        for (int k = 0; k < CC; k++) a += orow[k] * sWout[c * CC + k];
        const float x = sval_i * sew[c] + seb[c] + spos[lane * 33 + c];
        y[cc] = a + x;
        part += y[cc];
    }
    pmu[w][lane] = part;
    __syncthreads();
    float mu = 0.f;
    #pragma unroll
    for (int t = 0; t < 8; t++) mu += pmu[t][lane];
    mu *= (1.f / CC);
    float vp = 0.f;
    #pragma unroll
    for (int cc = 0; cc < 4; cc++) { float d = y[cc] - mu; vp += d * d; }
    pvar[w][lane] = vp;
    __syncthreads();
    float var = 0.f;
    #pragma unroll
    for (int t = 0; t < 8; t++) var += pvar[t][lane];
    var *= (1.f / CC);
    const float rs = rsqrtf(var + LN_EPS);

    float4 o4;
    o4.x = (y[0] - mu) * rs * sg[cb + 0] + sb2[cb + 0];
    o4.y = (y[1] - mu) * rs * sg[cb + 1] + sb2[cb + 1];
    o4.z = (y[2] - mu) * rs * sg[cb + 2] + sb2[cb + 2];
    o4.w = (y[3] - mu) * rs * sg[cb + 3] + sb2[cb + 3];
    *(float4*)&g_xbuf[((b * LL + i) * SS + s) * CC + cb] = o4;
}

// ---------------------------------------------------------------------------
// Kernel 2: column MHA (seq=4) + LN + mean over S.  grid = B*8 = 512, (256,4).
// ---------------------------------------------------------------------------
__global__ __launch_bounds__(256, 4)
void k_col_attn(const float* __restrict__ Win,  const float* __restrict__ bin,
                const float* __restrict__ Wout, const float* __restrict__ bout,
                const float* __restrict__ lng,  const float* __restrict__ lnb)
{
    __shared__ float sx[32 * 33];
    __shared__ float sk[32 * 33];
    __shared__ float sv[32 * 33];
    __shared__ float so[32 * 33];
    __shared__ float sWin[96 * CC];
    __shared__ float sWout[CC * CC];
    __shared__ float sbin[96];
    __shared__ float sbo[CC], sg[CC], sb2[CC];
    __shared__ float pmu[8][32], pvar[8][32];

    const int blk = blockIdx.x;
    const int b = blk >> 3;
    const int lg = blk & 7;
    const int tid = threadIdx.x;
    const int w = tid >> 5;
    const int tk = tid & 31;
    const int h = w & 3;
    const int sp = w >> 2;

    const int gb = (b * 64 + lg * 8) * SS * CC;
    for (int t = tid; t < 1024; t += 256)
        sx[(t >> 5) * 33 + (t & 31)] = g_xbuf[gb + t];
    for (int t = tid; t < 96 * CC; t += 256) sWin[t] = Win[t];
    for (int t = tid; t < CC * CC; t += 256) sWout[t] = Wout[t];
    if (tid < 96) sbin[tid] = bin[tid];
    if (tid < CC) { sbo[tid] = bout[tid]; sg[tid] = lng[tid]; sb2[tid] = lnb[tid]; }
    __syncthreads();

    float xr[CC];
    #pragma unroll
    for (int c = 0; c < CC; c++) xr[c] = sx[tk * 33 + c];

    float q[DD];
    if (sp == 0) {
        #pragma unroll
        for (int d = 0; d < DD; d++) {
            const int r = h * DD + d;
            float a = sbin[r];
            #pragma unroll
            for (int c = 0; c < CC; c++) a += xr[c] * sWin[r * CC + c];
            q[d] = a;
        }
    } else {
        #pragma unroll
        for (int d = 0; d < DD; d++) {
            const int r = CC + h * DD + d;
            float a = sbin[r];
            #pragma unroll
            for (int c = 0; c < CC; c++) a += xr[c] * sWin[r * CC + c];
            sk[tk * 33 + h * DD + d] = a;
        }
        #pragma unroll
        for (int d = 0; d < DD; d++) {
            const int r = 2 * CC + h * DD + d;
            float a = sbin[r];
            #pragma unroll
            for (int c = 0; c < CC; c++) a += xr[c] * sWin[r * CC + c];
            sv[tk * 33 + h * DD + d] = a;
        }
    }
    __syncthreads();

    if (sp == 0) {
        const float scale = 0.3535533905932738f;
        const int base = tk & ~3;
        float se = 0.f;
        float acc[DD];
        #pragma unroll
        for (int d = 0; d < DD; d++) acc[d] = 0.f;
        #pragma unroll
        for (int j = 0; j < SS; j++) {
            float a = 0.f;
            #pragma unroll
            for (int d = 0; d < DD; d++) a += q[d] * sk[(base + j) * 33 + h * DD + d];
            float p = __expf(a * scale);
            se += p;
            #pragma unroll
            for (int d = 0; d < DD; d++) acc[d] += p * sv[(base + j) * 33 + h * DD + d];
        }
        const float inv = __fdividef(1.f, se);
        #pragma unroll
        for (int d = 0; d < DD; d++) so[tk * 33 + h * DD + d] = acc[d] * inv;
    }
    __syncthreads();

    float orow[CC];
    #pragma unroll
    for (int k = 0; k < CC; k++) orow[k] = so[tk * 33 + k];
    const int cb = h * DD + sp * 4;
    float y[4];
    float part = 0.f;
    #pragma unroll
    for (int cc = 0; cc < 4; cc++) {
        const int c = cb + cc;
        float a = sbo[c];
        #pragma unroll
        for (int k = 0; k < CC; k++) a += orow[k] * sWout[c * CC + k];
        y[cc] = a + sx[tk * 33 + c];
        part += y[cc];
    }
    pmu[w][tk] = part;
    __syncthreads();
    float mu = 0.f;
    #pragma unroll
    for (int t = 0; t < 8; t++) mu += pmu[t][tk];
    mu *= (1.f / CC);
    float vp = 0.f;
    #pragma unroll
    for (int cc = 0; cc < 4; cc++) { float d = y[cc] - mu; vp += d * d; }
    pvar[w][tk] = vp;
    __syncthreads();
    float var = 0.f;
    #pragma unroll
    for (int t = 0; t < 8; t++) var += pvar[t][tk];
    var *= (1.f / CC);
    const float rs = rsqrtf(var + LN_EPS);

    float m0[4];
    #pragma unroll
    for (int cc = 0; cc < 4; cc++) {
        float v = (y[cc] - mu) * rs * sg[cb + cc] + sb2[cb + cc];
        v += __shfl_xor_sync(0xffffffffu, v, 1);
        v += __shfl_xor_sync(0xffffffffu, v, 2);
        m0[cc] = v * 0.25f;
    }
    if ((tk & 3) == 0) {
        const int l = lg * 8 + (tk >> 2);
        *(float4*)&g_m[(b * LL + l) * CC + cb] = make_float4(m0[0], m0[1], m0[2], m0[3]);
    }
}

// ---------------------------------------------------------------------------
// Kernel 3: R9 configuration (validated optimum: 64 regs, 4 blocks/SM).
// grid = B*8 = 512 (8 i's/block), block = 256.
// Phase 1: u GEMM (register-tiled, Wp L1-hot).
// Phase 2: parallel 2-j outputs (best LDS amortization).
// ---------------------------------------------------------------------------
__global__ __launch_bounds__(256, 4)
void k_pair(const float* __restrict__ Wp, const float* __restrict__ bp,
            const float* __restrict__ png, const float* __restrict__ pnb,
            float* __restrict__ out)
{
    __shared__ __align__(16) float sm[LL * 36];
    __shared__ __align__(16) float su[8 * 512];
    __shared__ float snrm[LL];
    __shared__ float sbp[CPD], sg[CPD], sb[CPD];

    const int b  = blockIdx.x >> 3;
    const int ch = blockIdx.x & 7;
    const int tid = threadIdx.x;
    const int ib = ch * 8;

    for (int t = tid; t < LL * CC; t += 256)
        sm[(t >> 5) * 36 + (t & 31)] = g_m[b * (LL * CC) + t];
    if (tid < CPD) { sbp[tid] = bp[tid]; sg[tid] = png[tid]; sb[tid] = pnb[tid]; }
    __syncthreads();

    if (tid < LL) {
        float a = 0.f;
        #pragma unroll
        for (int c = 0; c < CC; c++) { float v = sm[tid * 36 + c]; a += v * v; }
        snrm[tid] = sqrtf(a);
    }

    // phase 1: u for 8 i's. thread -> (p0, c2) and (p0+8, c2).
    {
        const int p0 = tid >> 5;           // 0..7 (warp-uniform)
        const int c2 = tid & 31;
        float a0[8], a1[8];
        #pragma unroll
        for (int il = 0; il < 8; il++) { a0[il] = 0.f; a1[il] = 0.f; }
        #pragma unroll 8
        for (int c1 = 0; c1 < CC; c1++) {
            const float w0 = Wp[p0 * 1024 + c1 * CC + c2];
            const float w1 = Wp[(p0 + 8) * 1024 + c1 * CC + c2];
            #pragma unroll
            for (int il = 0; il < 8; il++) {
                const float mv = sm[(ib + il) * 36 + c1];   // uniform broadcast
                a0[il] += mv * w0;
                a1[il] += mv * w1;
            }
        }
        #pragma unroll
        for (int il = 0; il < 8; il++) {
            su[il * 512 + p0 * CC + c2]       = a0[il];
            su[il * 512 + (p0 + 8) * CC + c2] = a1[il];
        }
    }
    __syncthreads();

    // phase 2: thread = (il, jl); outputs (i, jl) and (i, jl+32) in parallel
    const int il = tid >> 5;           // 0..7 (warp-uniform)
    const int jl = tid & 31;
    const int i  = ib + il;
    const int ja = jl, jb = jl + 32;

    float fa[CPD], fb[CPD];
    #pragma unroll
    for (int p = 0; p < CPD; p++) { fa[p] = 0.f; fb[p] = 0.f; }

    #pragma unroll
    for (int c4 = 0; c4 < 8; c4++) {
        const float4 ma = *(const float4*)&sm[ja * 36 + c4 * 4];  // conflict-free
        const float4 mb = *(const float4*)&sm[jb * 36 + c4 * 4];
        #pragma unroll
        for (int p = 0; p < CPD; p++) {
            const float4 u4 = *(const float4*)&su[il * 512 + p * CC + c4 * 4]; // broadcast
            fa[p] += u4.x * ma.x + u4.y * ma.y + u4.z * ma.z + u4.w * ma.w;
            fb[p] += u4.x * mb.x + u4.y * mb.y + u4.z * mb.z + u4.w * mb.w;
        }
    }

    const float ni = snrm[i];
    const float inva = __fdividef(1.f, fmaxf(ni * snrm[ja], 1e-6f));
    const float invb = __fdividef(1.f, fmaxf(ni * snrm[jb], 1e-6f));

    float mua = 0.f, mub = 0.f;
    #pragma unroll
    for (int p = 0; p < CPD; p++) {
        fa[p] = fa[p] * inva + sbp[p];
        fb[p] = fb[p] * invb + sbp[p];
        mua += fa[p];
        mub += fb[p];
    }
    mua *= (1.f / CPD); mub *= (1.f / CPD);
    float va = 0.f, vb = 0.f;
    #pragma unroll
    for (int p = 0; p < CPD; p++) {
        float da = fa[p] - mua; va += da * da;
        float db = fb[p] - mub; vb += db * db;
    }
    const float rsa = rsqrtf(va * (1.f / CPD) + LN_EPS);
    const float rsb = rsqrtf(vb * (1.f / CPD) + LN_EPS);
    #pragma unroll
    for (int p = 0; p < CPD; p++) {
        const int obase = ((b * CPD + p) * LL + i) * LL;
        float xa = (fa[p] - mua) * rsa * sg[p] + sb[p];
        float xb = (fb[p] - mub) * rsb * sg[p] + sb[p];
        out[obase + ja] = silu(xa);
        out[obase + jb] = silu(xb);
    }
}

// ---------------------------------------------------------------------------
extern "C" void kernel_launch(void* const* d_in, const int* in_sizes, int n_in,
                              void* d_out, int out_size)
{
    const float* ctcf = (const float*)d_in[0];
    const float* hac  = (const float*)d_in[1];
    const float* me1  = (const float*)d_in[2];
    const float* me3  = (const float*)d_in[3];
    const float* ew   = (const float*)d_in[4];
    const float* eb   = (const float*)d_in[5];
    const float* pos  = (const float*)d_in[6];
    const float* riw  = (const float*)d_in[7];
    const float* rib  = (const float*)d_in[8];
    const float* row_ = (const float*)d_in[9];
    const float* rob  = (const float*)d_in[10];
    const float* rlg  = (const float*)d_in[11];
    const float* rlb  = (const float*)d_in[12];
    const float* ciw  = (const float*)d_in[13];
    const float* cib  = (const float*)d_in[14];
    const float* cow  = (const float*)d_in[15];
    const float* cob  = (const float*)d_in[16];
    const float* clg  = (const float*)d_in[17];
    const float* clb  = (const float*)d_in[18];
    const float* pw   = (const float*)d_in[19];
    const float* pb   = (const float*)d_in[20];
    const float* plg  = (const float*)d_in[21];
    const float* plb  = (const float*)d_in[22];
    float* out = (float*)d_out;

    k_pre<<<96, 64>>>(riw, rib, eb, pos, ew);
    k_pre2<<<256, 64>>>();
    k_row_attn<<<BB * SS * 2, 256>>>(ctcf, hac, me1, me3, ew, eb, pos,
                                     row_, rob, rlg, rlb);
    k_col_attn<<<BB * 8, 256>>>(ciw, cib, cow, cob, clg, clb);
    k_pair<<<BB * 8, 256>>>(pw, pb, plg, plb, out);
}

// round 15
// speedup vs baseline: 1.1238x; 1.0877x over previous
#include <cuda_runtime.h>
#include <math.h>

#define BB 64
#define SS 4
#define LL 64
#define CC 32
#define HH 4
#define DD 8
#define CPD 16
#define LN_EPS 1e-5f

__device__ float g_xbuf[BB * LL * SS * CC];   // (b,l,s,c) after row attention
__device__ float g_m[BB * LL * CC];           // (b,l,c) track-mean
__device__ float g_we[96];                    // Win · ew  per row
__device__ float g_wcR[96 * 64];              // [r][i] = Win_r·(eb+pos_i)+b_r
__device__ float g_wcT[64 * 96];              // token-major [i][r]

__device__ __forceinline__ float dot4(float4 a, float4 b) {
    return a.x * b.x + a.y * b.y + a.z * b.z + a.w * b.w;
}

// SiLU via tanh.approx: x*sigmoid(x) = h*tanh(h)+h with h=x/2 (1 MUFU, 3 issues)
__device__ __forceinline__ float silu(float x) {
    float h = 0.5f * x, t;
    asm("tanh.approx.f32 %0, %1;" : "=f"(t) : "f"(h));
    return fmaf(h, t, h);
}

// ---------------------------------------------------------------------------
// k_pre: position-constant projection tables (row attention is rank-1 in data)
// ---------------------------------------------------------------------------
__global__ __launch_bounds__(64)
void k_pre(const float* __restrict__ Win, const float* __restrict__ bin,
           const float* __restrict__ eb,  const float* __restrict__ pos,
           const float* __restrict__ ew)
{
    const int r = blockIdx.x;
    const int i = threadIdx.x;
    float a = bin[r];
    #pragma unroll
    for (int c = 0; c < CC; c++)
        a += Win[r * CC + c] * (eb[c] + pos[i * CC + c]);
    g_wcR[r * 64 + i] = a;
    g_wcT[i * 96 + r] = a;
    if (i == 0) {
        float e = 0.f;
        #pragma unroll
        for (int c = 0; c < CC; c++) e += Win[r * CC + c] * ew[c];
        g_we[r] = e;
    }
}

// ---------------------------------------------------------------------------
// Kernel 1: row MHA + residual LN.  grid = B*S*2 = 512, single wave (256,4).
// (R9 configuration — validated best)
// ---------------------------------------------------------------------------
__global__ __launch_bounds__(256, 4)
void k_row_attn(const float* __restrict__ ctcf, const float* __restrict__ hac,
                const float* __restrict__ me1,  const float* __restrict__ me3,
                const float* __restrict__ ew,   const float* __restrict__ eb,
                const float* __restrict__ pos,
                const float* __restrict__ Wout, const float* __restrict__ bout,
                const float* __restrict__ lng,  const float* __restrict__ lnb)
{
    __shared__ __align__(16) float sk[LL * 36];
    __shared__ __align__(16) float sv[LL * 36];
    __shared__ float so[32 * 33];
    __shared__ float spos[32 * 33];
    __shared__ float sWout[CC * CC];
    __shared__ float pacc[HH][32][9];
    __shared__ float pmu[8][32], pvar[8][32];
    __shared__ float ssval[LL];
    __shared__ float sbo[CC], sg[CC], sb2[CC], sew[CC], seb[CC];

    const int blk = blockIdx.x;
    const int b = blk >> 3;
    const int s = (blk >> 1) & 3;
    const int ihalf = blk & 1;
    const int tid = threadIdx.x;
    const int w = tid >> 5;
    const int lane = tid & 31;
    const int h = w & 3;
    const int jh = w >> 2;
    const int i = ihalf * 32 + lane;

    const float* sig = (s == 0) ? ctcf : (s == 1) ? hac : (s == 2) ? me1 : me3;
    if (tid < 64) ssval[tid] = sig[b * LL + tid];
    for (int t = tid; t < CC * CC; t += 256) sWout[t] = Wout[t];
    if (tid < CC) {
        sbo[tid] = bout[tid]; sg[tid] = lng[tid]; sb2[tid] = lnb[tid];
        sew[tid] = ew[tid];  seb[tid] = eb[tid];
    }
    for (int t = tid; t < 1024; t += 256)
        spos[(t >> 5) * 33 + (t & 31)] = pos[ihalf * 1024 + t];
    __syncthreads();

    for (int t = tid; t < 2048; t += 256) {
        const int j = t >> 5, d = t & 31;
        const float sj = ssval[j];
        sk[j * 36 + d] = sj * g_we[32 + d] + g_wcT[j * 96 + 32 + d];
        sv[j * 36 + d] = sj * g_we[64 + d] + g_wcT[j * 96 + 64 + d];
    }
    const float sval_i = ssval[i];
    float q[DD];
    #pragma unroll
    for (int d = 0; d < DD; d++)
        q[d] = sval_i * g_we[h * DD + d] + g_wcR[(h * DD + d) * 64 + i];
    __syncthreads();

    const float scale = 0.3535533905932738f;
    float se = 0.f;
    float acc[DD];
    #pragma unroll
    for (int d = 0; d < DD; d++) acc[d] = 0.f;
    const int j0 = jh * 32;
    #pragma unroll 4
    for (int jj = 0; jj < 32; jj++) {
        const int j = j0 + jj;
        float4 k0 = *(const float4*)&sk[j * 36 + h * DD];
        float4 k1 = *(const float4*)&sk[j * 36 + h * DD + 4];
        float a = q[0]*k0.x + q[1]*k0.y + q[2]*k0.z + q[3]*k0.w
                + q[4]*k1.x + q[5]*k1.y + q[6]*k1.z + q[7]*k1.w;
        float p = __expf(a * scale);
        se += p;
        float4 v0 = *(const float4*)&sv[j * 36 + h * DD];
        float4 v1 = *(const float4*)&sv[j * 36 + h * DD + 4];
        acc[0] += p * v0.x; acc[1] += p * v0.y; acc[2] += p * v0.z; acc[3] += p * v0.w;
        acc[4] += p * v1.x; acc[5] += p * v1.y; acc[6] += p * v1.z; acc[7] += p * v1.w;
    }
    if (jh == 1) {
        #pragma unroll
        for (int d = 0; d < DD; d++) pacc[h][lane][d] = acc[d];
        pacc[h][lane][8] = se;
    }
    __syncthreads();
    if (jh == 0) {
        se += pacc[h][lane][8];
        #pragma unroll
        for (int d = 0; d < DD; d++) acc[d] += pacc[h][lane][d];
        const float inv = __fdividef(1.f, se);
        #pragma unroll
        for (int d = 0; d < DD; d++) so[lane * 33 + h * DD + d] = acc[d] * inv;
    }
    __syncthreads();

    float orow[CC];
    #pragma unroll
    for (int k = 0; k < CC; k++) orow[k] = so[lane * 33 + k];
    const int cb = h * DD + jh * 4;
    float y[4];
    float part = 0.f;
    #pragma unroll
    for (int cc = 0; cc < 4; cc++) {
        const int c = cb + cc;
        float a = sbo[c];
        #pragma unroll
        for (int k = 0; k < CC; k++) a += orow[k] * sWout[c * CC + k];
        const float x = sval_i * sew[c] + seb[c] + spos[lane * 33 + c];
        y[cc] = a + x;
        part += y[cc];
    }
    pmu[w][lane] = part;
    __syncthreads();
    float mu = 0.f;
    #pragma unroll
    for (int t = 0; t < 8; t++) mu += pmu[t][lane];
    mu *= (1.f / CC);
    float vp = 0.f;
    #pragma unroll
    for (int cc = 0; cc < 4; cc++) { float d = y[cc] - mu; vp += d * d; }
    pvar[w][lane] = vp;
    __syncthreads();
    float var = 0.f;
    #pragma unroll
    for (int t = 0; t < 8; t++) var += pvar[t][lane];
    var *= (1.f / CC);
    const float rs = rsqrtf(var + LN_EPS);

    float4 o4;
    o4.x = (y[0] - mu) * rs * sg[cb + 0] + sb2[cb + 0];
    o4.y = (y[1] - mu) * rs * sg[cb + 1] + sb2[cb + 1];
    o4.z = (y[2] - mu) * rs * sg[cb + 2] + sb2[cb + 2];
    o4.w = (y[3] - mu) * rs * sg[cb + 3] + sb2[cb + 3];
    *(float4*)&g_xbuf[((b * LL + i) * SS + s) * CC + cb] = o4;
}

// ---------------------------------------------------------------------------
// Kernel 2: column MHA (seq=4) + LN + mean over S.  grid = B*8 = 512, (256,4).
// REWORKED: float4 weight reads (4x fewer LDS), balanced 12/12 sp-split.
// ---------------------------------------------------------------------------
__global__ __launch_bounds__(256, 4)
void k_col_attn(const float* __restrict__ Win,  const float* __restrict__ bin,
                const float* __restrict__ Wout, const float* __restrict__ bout,
                const float* __restrict__ lng,  const float* __restrict__ lnb)
{
    __shared__ __align__(16) float sx[32 * 36];
    __shared__ float sk[32 * 33];
    __shared__ float sv[32 * 33];
    __shared__ float so[32 * 33];
    __shared__ __align__(16) float sWin[96 * CC];
    __shared__ __align__(16) float sWout[CC * CC];
    __shared__ float sbin[96];
    __shared__ float sbo[CC], sg[CC], sb2[CC];
    __shared__ float pmu[8][32], pvar[8][32];

    const int blk = blockIdx.x;
    const int b = blk >> 3;
    const int lg = blk & 7;
    const int tid = threadIdx.x;
    const int w = tid >> 5;
    const int tk = tid & 31;
    const int h = w & 3;
    const int sp = w >> 2;

    const int gb = (b * 64 + lg * 8) * SS * CC;
    for (int t = tid; t < 1024; t += 256)
        sx[(t >> 5) * 36 + (t & 31)] = g_xbuf[gb + t];
    for (int t = tid; t < 96 * CC; t += 256) sWin[t] = Win[t];
    for (int t = tid; t < CC * CC; t += 256) sWout[t] = Wout[t];
    if (tid < 96) sbin[tid] = bin[tid];
    if (tid < CC) { sbo[tid] = bout[tid]; sg[tid] = lng[tid]; sb2[tid] = lnb[tid]; }
    __syncthreads();

    // x row in float4 regs (stride-36 rows: conflict-free LDS.128)
    float4 xr4[8];
    #pragma unroll
    for (int c4 = 0; c4 < 8; c4++) xr4[c4] = *(const float4*)&sx[tk * 36 + c4 * 4];

    // balanced projections: sp=0 -> q(8)+k(0..3); sp=1 -> k(4..7)+v(8). 12 rows each.
    float q[DD];
    if (sp == 0) {
        #pragma unroll
        for (int d = 0; d < DD; d++) {
            const int r = h * DD + d;
            const float4* wv = (const float4*)&sWin[r * CC];
            float a = sbin[r];
            #pragma unroll
            for (int c4 = 0; c4 < 8; c4++) a += dot4(xr4[c4], wv[c4]);
            q[d] = a;
        }
        #pragma unroll
        for (int d = 0; d < 4; d++) {
            const int r = CC + h * DD + d;
            const float4* wv = (const float4*)&sWin[r * CC];
            float a = sbin[r];
            #pragma unroll
            for (int c4 = 0; c4 < 8; c4++) a += dot4(xr4[c4], wv[c4]);
            sk[tk * 33 + h * DD + d] = a;
        }
    } else {
        #pragma unroll
        for (int d = 4; d < DD; d++) {
            const int r = CC + h * DD + d;
            const float4* wv = (const float4*)&sWin[r * CC];
            float a = sbin[r];
            #pragma unroll
            for (int c4 = 0; c4 < 8; c4++) a += dot4(xr4[c4], wv[c4]);
            sk[tk * 33 + h * DD + d] = a;
        }
        #pragma unroll
        for (int d = 0; d < DD; d++) {
            const int r = 2 * CC + h * DD + d;
            const float4* wv = (const float4*)&sWin[r * CC];
            float a = sbin[r];
            #pragma unroll
            for (int c4 = 0; c4 < 8; c4++) a += dot4(xr4[c4], wv[c4]);
            sv[tk * 33 + h * DD + d] = a;
        }
    }
    __syncthreads();

    if (sp == 0) {
        const float scale = 0.3535533905932738f;
        const int base = tk & ~3;
        float se = 0.f;
        float acc[DD];
        #pragma unroll
        for (int d = 0; d < DD; d++) acc[d] = 0.f;
        #pragma unroll
        for (int j = 0; j < SS; j++) {
            float a = 0.f;
            #pragma unroll
            for (int d = 0; d < DD; d++) a += q[d] * sk[(base + j) * 33 + h * DD + d];
            float p = __expf(a * scale);
            se += p;
            #pragma unroll
            for (int d = 0; d < DD; d++) acc[d] += p * sv[(base + j) * 33 + h * DD + d];
        }
        const float inv = __fdividef(1.f, se);
        #pragma unroll
        for (int d = 0; d < DD; d++) so[tk * 33 + h * DD + d] = acc[d] * inv;
    }
    __syncthreads();

    float orow[CC];
    #pragma unroll
    for (int k = 0; k < CC; k++) orow[k] = so[tk * 33 + k];
    const int cb = h * DD + sp * 4;
    float y[4];
    float part = 0.f;
    #pragma unroll
    for (int cc = 0; cc < 4; cc++) {
        const int c = cb + cc;
        const float4* wv = (const float4*)&sWout[c * CC];
        float a = sbo[c];
        #pragma unroll
        for (int k4 = 0; k4 < 8; k4++)
            a += orow[k4*4] * wv[k4].x + orow[k4*4+1] * wv[k4].y
               + orow[k4*4+2] * wv[k4].z + orow[k4*4+3] * wv[k4].w;
        y[cc] = a + sx[tk * 36 + c];
        part += y[cc];
    }
    pmu[w][tk] = part;
    __syncthreads();
    float mu = 0.f;
    #pragma unroll
    for (int t = 0; t < 8; t++) mu += pmu[t][tk];
    mu *= (1.f / CC);
    float vp = 0.f;
    #pragma unroll
    for (int cc = 0; cc < 4; cc++) { float d = y[cc] - mu; vp += d * d; }
    pvar[w][tk] = vp;
    __syncthreads();
    float var = 0.f;
    #pragma unroll
    for (int t = 0; t < 8; t++) var += pvar[t][tk];
    var *= (1.f / CC);
    const float rs = rsqrtf(var + LN_EPS);

    float m0[4];
    #pragma unroll
    for (int cc = 0; cc < 4; cc++) {
        float v = (y[cc] - mu) * rs * sg[cb + cc] + sb2[cb + cc];
        v += __shfl_xor_sync(0xffffffffu, v, 1);
        v += __shfl_xor_sync(0xffffffffu, v, 2);
        m0[cc] = v * 0.25f;
    }
    if ((tk & 3) == 0) {
        const int l = lg * 8 + (tk >> 2);
        *(float4*)&g_m[(b * LL + l) * CC + cb] = make_float4(m0[0], m0[1], m0[2], m0[3]);
    }
}

// ---------------------------------------------------------------------------
// Kernel 3: R9 configuration (validated optimum: 64 regs, 4 blocks/SM).
// ---------------------------------------------------------------------------
__global__ __launch_bounds__(256, 4)
void k_pair(const float* __restrict__ Wp, const float* __restrict__ bp,
            const float* __restrict__ png, const float* __restrict__ pnb,
            float* __restrict__ out)
{
    __shared__ __align__(16) float sm[LL * 36];
    __shared__ __align__(16) float su[8 * 512];
    __shared__ float snrm[LL];
    __shared__ float sbp[CPD], sg[CPD], sb[CPD];

    const int b  = blockIdx.x >> 3;
    const int ch = blockIdx.x & 7;
    const int tid = threadIdx.x;
    const int ib = ch * 8;

    for (int t = tid; t < LL * CC; t += 256)
        sm[(t >> 5) * 36 + (t & 31)] = g_m[b * (LL * CC) + t];
    if (tid < CPD) { sbp[tid] = bp[tid]; sg[tid] = png[tid]; sb[tid] = pnb[tid]; }
    __syncthreads();

    if (tid < LL) {
        float a = 0.f;
        #pragma unroll
        for (int c = 0; c < CC; c++) { float v = sm[tid * 36 + c]; a += v * v; }
        snrm[tid] = sqrtf(a);
    }

    // phase 1: u for 8 i's. thread -> (p0, c2) and (p0+8, c2).
    {
        const int p0 = tid >> 5;
        const int c2 = tid & 31;
        float a0[8], a1[8];
        #pragma unroll
        for (int il = 0; il < 8; il++) { a0[il] = 0.f; a1[il] = 0.f; }
        #pragma unroll 8
        for (int c1 = 0; c1 < CC; c1++) {
            const float w0 = Wp[p0 * 1024 + c1 * CC + c2];
            const float w1 = Wp[(p0 + 8) * 1024 + c1 * CC + c2];
            #pragma unroll
            for (int il = 0; il < 8; il++) {
                const float mv = sm[(ib + il) * 36 + c1];
                a0[il] += mv * w0;
                a1[il] += mv * w1;
            }
        }
        #pragma unroll
        for (int il = 0; il < 8; il++) {
            su[il * 512 + p0 * CC + c2]       = a0[il];
            su[il * 512 + (p0 + 8) * CC + c2] = a1[il];
        }
    }
    __syncthreads();

    // phase 2: thread = (il, jl); outputs (i, jl) and (i, jl+32) in parallel
    const int il = tid >> 5;
    const int jl = tid & 31;
    const int i  = ib + il;
    const int ja = jl, jb = jl + 32;

    float fa[CPD], fb[CPD];
    #pragma unroll
    for (int p = 0; p < CPD; p++) { fa[p] = 0.f; fb[p] = 0.f; }

    #pragma unroll
    for (int c4 = 0; c4 < 8; c4++) {
        const float4 ma = *(const float4*)&sm[ja * 36 + c4 * 4];
        const float4 mb = *(const float4*)&sm[jb * 36 + c4 * 4];
        #pragma unroll
        for (int p = 0; p < CPD; p++) {
            const float4 u4 = *(const float4*)&su[il * 512 + p * CC + c4 * 4];
            fa[p] += u4.x * ma.x + u4.y * ma.y + u4.z * ma.z + u4.w * ma.w;
            fb[p] += u4.x * mb.x + u4.y * mb.y + u4.z * mb.z + u4.w * mb.w;
        }
    }

    const float ni = snrm[i];
    const float inva = __fdividef(1.f, fmaxf(ni * snrm[ja], 1e-6f));
    const float invb = __fdividef(1.f, fmaxf(ni * snrm[jb], 1e-6f));

    float mua = 0.f, mub = 0.f;
    #pragma unroll
    for (int p = 0; p < CPD; p++) {
        fa[p] = fa[p] * inva + sbp[p];
        fb[p] = fb[p] * invb + sbp[p];
        mua += fa[p];
        mub += fb[p];
    }
    mua *= (1.f / CPD); mub *= (1.f / CPD);
    float va = 0.f, vb = 0.f;
    #pragma unroll
    for (int p = 0; p < CPD; p++) {
        float da = fa[p] - mua; va += da * da;
        float db = fb[p] - mub; vb += db * db;
    }
    const float rsa = rsqrtf(va * (1.f / CPD) + LN_EPS);
    const float rsb = rsqrtf(vb * (1.f / CPD) + LN_EPS);
    #pragma unroll
    for (int p = 0; p < CPD; p++) {
        const int obase = ((b * CPD + p) * LL + i) * LL;
        float xa = (fa[p] - mua) * rsa * sg[p] + sb[p];
        float xb = (fb[p] - mub) * rsb * sg[p] + sb[p];
        out[obase + ja] = silu(xa);
        out[obase + jb] = silu(xb);
    }
}

// ---------------------------------------------------------------------------
extern "C" void kernel_launch(void* const* d_in, const int* in_sizes, int n_in,
                              void* d_out, int out_size)
{
    const float* ctcf = (const float*)d_in[0];
    const float* hac  = (const float*)d_in[1];
    const float* me1  = (const float*)d_in[2];
    const float* me3  = (const float*)d_in[3];
    const float* ew   = (const float*)d_in[4];
    const float* eb   = (const float*)d_in[5];
    const float* pos  = (const float*)d_in[6];
    const float* riw  = (const float*)d_in[7];
    const float* rib  = (const float*)d_in[8];
    const float* row_ = (const float*)d_in[9];
    const float* rob  = (const float*)d_in[10];
    const float* rlg  = (const float*)d_in[11];
    const float* rlb  = (const float*)d_in[12];
    const float* ciw  = (const float*)d_in[13];
    const float* cib  = (const float*)d_in[14];
    const float* cow  = (const float*)d_in[15];
    const float* cob  = (const float*)d_in[16];
    const float* clg  = (const float*)d_in[17];
    const float* clb  = (const float*)d_in[18];
    const float* pw   = (const float*)d_in[19];
    const float* pb   = (const float*)d_in[20];
    const float* plg  = (const float*)d_in[21];
    const float* plb  = (const float*)d_in[22];
    float* out = (float*)d_out;

    k_pre<<<96, 64>>>(riw, rib, eb, pos, ew);
    k_row_attn<<<BB * SS * 2, 256>>>(ctcf, hac, me1, me3, ew, eb, pos,
                                     row_, rob, rlg, rlb);
    k_col_attn<<<BB * 8, 256>>>(ciw, cib, cow, cob, clg, clb);
    k_pair<<<BB * 8, 256>>>(pw, pb, plg, plb, out);
}

// round 16
// speedup vs baseline: 1.2240x; 1.0892x over previous
#include <cuda_runtime.h>
#include <math.h>

#define BB 64
#define SS 4
#define LL 64
#define CC 32
#define HH 4
#define DD 8
#define CPD 16
#define LN_EPS 1e-5f

__device__ float g_xbuf[BB * LL * SS * CC];   // (b,l,s,c) after row attention
__device__ float g_m[BB * LL * CC];           // (b,l,c) track-mean
__device__ float g_we[96];                    // Win · ew  per row
__device__ float g_wcR[96 * 64];              // [r][i] = Win_r·(eb+pos_i)+b_r
__device__ float g_wcT[64 * 96];              // token-major [i][r]

__device__ __forceinline__ float dot4(float4 a, float4 b) {
    return a.x * b.x + a.y * b.y + a.z * b.z + a.w * b.w;
}

// SiLU via tanh.approx: x*sigmoid(x) = h*tanh(h)+h with h=x/2 (1 MUFU, 3 issues)
__device__ __forceinline__ float silu(float x) {
    float h = 0.5f * x, t;
    asm("tanh.approx.f32 %0, %1;" : "=f"(t) : "f"(h));
    return fmaf(h, t, h);
}

// ---------------------------------------------------------------------------
// k_pre: position-constant projection tables (row attention is rank-1 in data)
// ---------------------------------------------------------------------------
__global__ __launch_bounds__(64)
void k_pre(const float* __restrict__ Win, const float* __restrict__ bin,
           const float* __restrict__ eb,  const float* __restrict__ pos,
           const float* __restrict__ ew)
{
    const int r = blockIdx.x;
    const int i = threadIdx.x;
    float a = bin[r];
    #pragma unroll
    for (int c = 0; c < CC; c++)
        a += Win[r * CC + c] * (eb[c] + pos[i * CC + c]);
    g_wcR[r * 64 + i] = a;
    g_wcT[i * 96 + r] = a;
    if (i == 0) {
        float e = 0.f;
        #pragma unroll
        for (int c = 0; c < CC; c++) e += Win[r * CC + c] * ew[c];
        g_we[r] = e;
    }
    cudaTriggerProgrammaticLaunchCompletion();
}

// ---------------------------------------------------------------------------
// Kernel 1: row MHA + residual LN.  grid = B*S*2 = 512, single wave (256,4).
// PDL consumer of k_pre (g_we/g_wcR/g_wcT), PDL producer for k_col.
// ---------------------------------------------------------------------------
__global__ __launch_bounds__(256, 4)
void k_row_attn(const float* __restrict__ ctcf, const float* __restrict__ hac,
                const float* __restrict__ me1,  const float* __restrict__ me3,
                const float* __restrict__ ew,   const float* __restrict__ eb,
                const float* __restrict__ pos,
                const float* __restrict__ Wout, const float* __restrict__ bout,
                const float* __restrict__ lng,  const float* __restrict__ lnb)
{
    __shared__ __align__(16) float sk[LL * 36];
    __shared__ __align__(16) float sv[LL * 36];
    __shared__ float so[32 * 33];
    __shared__ float spos[32 * 33];
    __shared__ float sWout[CC * CC];
    __shared__ float pacc[HH][32][9];
    __shared__ float pmu[8][32], pvar[8][32];
    __shared__ float ssval[LL];
    __shared__ float sbo[CC], sg[CC], sb2[CC], sew[CC], seb[CC];

    const int blk = blockIdx.x;
    const int b = blk >> 3;
    const int s = (blk >> 1) & 3;
    const int ihalf = blk & 1;
    const int tid = threadIdx.x;
    const int w = tid >> 5;
    const int lane = tid & 31;
    const int h = w & 3;
    const int jh = w >> 2;
    const int i = ihalf * 32 + lane;

    // prologue: loads that do NOT depend on k_pre output
    const float* sig = (s == 0) ? ctcf : (s == 1) ? hac : (s == 2) ? me1 : me3;
    if (tid < 64) ssval[tid] = sig[b * LL + tid];
    for (int t = tid; t < CC * CC; t += 256) sWout[t] = Wout[t];
    if (tid < CC) {
        sbo[tid] = bout[tid]; sg[tid] = lng[tid]; sb2[tid] = lnb[tid];
        sew[tid] = ew[tid];  seb[tid] = eb[tid];
    }
    for (int t = tid; t < 1024; t += 256)
        spos[(t >> 5) * 33 + (t & 31)] = pos[ihalf * 1024 + t];
    __syncthreads();

    // wait for k_pre's tables, then release k_col's launch
    cudaGridDependencySynchronize();
    cudaTriggerProgrammaticLaunchCompletion();

    for (int t = tid; t < 2048; t += 256) {
        const int j = t >> 5, d = t & 31;
        const float sj = ssval[j];
        sk[j * 36 + d] = sj * g_we[32 + d] + g_wcT[j * 96 + 32 + d];
        sv[j * 36 + d] = sj * g_we[64 + d] + g_wcT[j * 96 + 64 + d];
    }
    const float sval_i = ssval[i];
    float q[DD];
    #pragma unroll
    for (int d = 0; d < DD; d++)
        q[d] = sval_i * g_we[h * DD + d] + g_wcR[(h * DD + d) * 64 + i];
    __syncthreads();

    const float scale = 0.3535533905932738f;
    float se = 0.f;
    float acc[DD];
    #pragma unroll
    for (int d = 0; d < DD; d++) acc[d] = 0.f;
    const int j0 = jh * 32;
    #pragma unroll 4
    for (int jj = 0; jj < 32; jj++) {
        const int j = j0 + jj;
        float4 k0 = *(const float4*)&sk[j * 36 + h * DD];
        float4 k1 = *(const float4*)&sk[j * 36 + h * DD + 4];
        float a = q[0]*k0.x + q[1]*k0.y + q[2]*k0.z + q[3]*k0.w
                + q[4]*k1.x + q[5]*k1.y + q[6]*k1.z + q[7]*k1.w;
        float p = __expf(a * scale);
        se += p;
        float4 v0 = *(const float4*)&sv[j * 36 + h * DD];
        float4 v1 = *(const float4*)&sv[j * 36 + h * DD + 4];
        acc[0] += p * v0.x; acc[1] += p * v0.y; acc[2] += p * v0.z; acc[3] += p * v0.w;
        acc[4] += p * v1.x; acc[5] += p * v1.y; acc[6] += p * v1.z; acc[7] += p * v1.w;
    }
    if (jh == 1) {
        #pragma unroll
        for (int d = 0; d < DD; d++) pacc[h][lane][d] = acc[d];
        pacc[h][lane][8] = se;
    }
    __syncthreads();
    if (jh == 0) {
        se += pacc[h][lane][8];
        #pragma unroll
        for (int d = 0; d < DD; d++) acc[d] += pacc[h][lane][d];
        const float inv = __fdividef(1.f, se);
        #pragma unroll
        for (int d = 0; d < DD; d++) so[lane * 33 + h * DD + d] = acc[d] * inv;
    }
    __syncthreads();

    float orow[CC];
    #pragma unroll
    for (int k = 0; k < CC; k++) orow[k] = so[lane * 33 + k];
    const int cb = h * DD + jh * 4;
    float y[4];
    float part = 0.f;
    #pragma unroll
    for (int cc = 0; cc < 4; cc++) {
        const int c = cb + cc;
        float a = sbo[c];
        #pragma unroll
        for (int k = 0; k < CC; k++) a += orow[k] * sWout[c * CC + k];
        const float x = sval_i * sew[c] + seb[c] + spos[lane * 33 + c];
        y[cc] = a + x;
        part += y[cc];
    }
    pmu[w][lane] = part;
    __syncthreads();
    float mu = 0.f;
    #pragma unroll
    for (int t = 0; t < 8; t++) mu += pmu[t][lane];
    mu *= (1.f / CC);
    float vp = 0.f;
    #pragma unroll
    for (int cc = 0; cc < 4; cc++) { float d = y[cc] - mu; vp += d * d; }
    pvar[w][lane] = vp;
    __syncthreads();
    float var = 0.f;
    #pragma unroll
    for (int t = 0; t < 8; t++) var += pvar[t][lane];
    var *= (1.f / CC);
    const float rs = rsqrtf(var + LN_EPS);

    float4 o4;
    o4.x = (y[0] - mu) * rs * sg[cb + 0] + sb2[cb + 0];
    o4.y = (y[1] - mu) * rs * sg[cb + 1] + sb2[cb + 1];
    o4.z = (y[2] - mu) * rs * sg[cb + 2] + sb2[cb + 2];
    o4.w = (y[3] - mu) * rs * sg[cb + 3] + sb2[cb + 3];
    *(float4*)&g_xbuf[((b * LL + i) * SS + s) * CC + cb] = o4;
}

// ---------------------------------------------------------------------------
// Kernel 2: column MHA (seq=4) + LN + mean over S.  grid = B*8 = 512, (256,4).
// PDL: weights loaded BEFORE the g_xbuf dependency sync.
// ---------------------------------------------------------------------------
__global__ __launch_bounds__(256, 4)
void k_col_attn(const float* __restrict__ Win,  const float* __restrict__ bin,
                const float* __restrict__ Wout, const float* __restrict__ bout,
                const float* __restrict__ lng,  const float* __restrict__ lnb)
{
    __shared__ __align__(16) float sx[32 * 36];
    __shared__ float sk[32 * 33];
    __shared__ float sv[32 * 33];
    __shared__ float so[32 * 33];
    __shared__ __align__(16) float sWin[96 * CC];
    __shared__ __align__(16) float sWout[CC * CC];
    __shared__ float sbin[96];
    __shared__ float sbo[CC], sg[CC], sb2[CC];
    __shared__ float pmu[8][32], pvar[8][32];

    const int blk = blockIdx.x;
    const int b = blk >> 3;
    const int lg = blk & 7;
    const int tid = threadIdx.x;
    const int w = tid >> 5;
    const int tk = tid & 31;
    const int h = w & 3;
    const int sp = w >> 2;

    // prologue: weight/bias loads (independent of k_row output)
    for (int t = tid; t < 96 * CC; t += 256) sWin[t] = Win[t];
    for (int t = tid; t < CC * CC; t += 256) sWout[t] = Wout[t];
    if (tid < 96) sbin[tid] = bin[tid];
    if (tid < CC) { sbo[tid] = bout[tid]; sg[tid] = lng[tid]; sb2[tid] = lnb[tid]; }

    // wait for k_row's g_xbuf, then release k_pair's launch
    cudaGridDependencySynchronize();
    cudaTriggerProgrammaticLaunchCompletion();

    const int gb = (b * 64 + lg * 8) * SS * CC;
    for (int t = tid; t < 1024; t += 256)
        sx[(t >> 5) * 36 + (t & 31)] = g_xbuf[gb + t];
    __syncthreads();

    float4 xr4[8];
    #pragma unroll
    for (int c4 = 0; c4 < 8; c4++) xr4[c4] = *(const float4*)&sx[tk * 36 + c4 * 4];

    // balanced projections: sp=0 -> q(8)+k(0..3); sp=1 -> k(4..7)+v(8)
    float q[DD];
    if (sp == 0) {
        #pragma unroll
        for (int d = 0; d < DD; d++) {
            const int r = h * DD + d;
            const float4* wv = (const float4*)&sWin[r * CC];
            float a = sbin[r];
            #pragma unroll
            for (int c4 = 0; c4 < 8; c4++) a += dot4(xr4[c4], wv[c4]);
            q[d] = a;
        }
        #pragma unroll
        for (int d = 0; d < 4; d++) {
            const int r = CC + h * DD + d;
            const float4* wv = (const float4*)&sWin[r * CC];
            float a = sbin[r];
            #pragma unroll
            for (int c4 = 0; c4 < 8; c4++) a += dot4(xr4[c4], wv[c4]);
            sk[tk * 33 + h * DD + d] = a;
        }
    } else {
        #pragma unroll
        for (int d = 4; d < DD; d++) {
            const int r = CC + h * DD + d;
            const float4* wv = (const float4*)&sWin[r * CC];
            float a = sbin[r];
            #pragma unroll
            for (int c4 = 0; c4 < 8; c4++) a += dot4(xr4[c4], wv[c4]);
            sk[tk * 33 + h * DD + d] = a;
        }
        #pragma unroll
        for (int d = 0; d < DD; d++) {
            const int r = 2 * CC + h * DD + d;
            const float4* wv = (const float4*)&sWin[r * CC];
            float a = sbin[r];
            #pragma unroll
            for (int c4 = 0; c4 < 8; c4++) a += dot4(xr4[c4], wv[c4]);
            sv[tk * 33 + h * DD + d] = a;
        }
    }
    __syncthreads();

    if (sp == 0) {
        const float scale = 0.3535533905932738f;
        const int base = tk & ~3;
        float se = 0.f;
        float acc[DD];
        #pragma unroll
        for (int d = 0; d < DD; d++) acc[d] = 0.f;
        #pragma unroll
        for (int j = 0; j < SS; j++) {
            float a = 0.f;
            #pragma unroll
            for (int d = 0; d < DD; d++) a += q[d] * sk[(base + j) * 33 + h * DD + d];
            float p = __expf(a * scale);
            se += p;
            #pragma unroll
            for (int d = 0; d < DD; d++) acc[d] += p * sv[(base + j) * 33 + h * DD + d];
        }
        const float inv = __fdividef(1.f, se);
        #pragma unroll
        for (int d = 0; d < DD; d++) so[tk * 33 + h * DD + d] = acc[d] * inv;
    }
    __syncthreads();

    float orow[CC];
    #pragma unroll
    for (int k = 0; k < CC; k++) orow[k] = so[tk * 33 + k];
    const int cb = h * DD + sp * 4;
    float y[4];
    float part = 0.f;
    #pragma unroll
    for (int cc = 0; cc < 4; cc++) {
        const int c = cb + cc;
        const float4* wv = (const float4*)&sWout[c * CC];
        float a = sbo[c];
        #pragma unroll
        for (int k4 = 0; k4 < 8; k4++)
            a += orow[k4*4] * wv[k4].x + orow[k4*4+1] * wv[k4].y
               + orow[k4*4+2] * wv[k4].z + orow[k4*4+3] * wv[k4].w;
        y[cc] = a + sx[tk * 36 + c];
        part += y[cc];
    }
    pmu[w][tk] = part;
    __syncthreads();
    float mu = 0.f;
    #pragma unroll
    for (int t = 0; t < 8; t++) mu += pmu[t][tk];
    mu *= (1.f / CC);
    float vp = 0.f;
    #pragma unroll
    for (int cc = 0; cc < 4; cc++) { float d = y[cc] - mu; vp += d * d; }
    pvar[w][tk] = vp;
    __syncthreads();
    float var = 0.f;
    #pragma unroll
    for (int t = 0; t < 8; t++) var += pvar[t][tk];
    var *= (1.f / CC);
    const float rs = rsqrtf(var + LN_EPS);

    float m0[4];
    #pragma unroll
    for (int cc = 0; cc < 4; cc++) {
        float v = (y[cc] - mu) * rs * sg[cb + cc] + sb2[cb + cc];
        v += __shfl_xor_sync(0xffffffffu, v, 1);
        v += __shfl_xor_sync(0xffffffffu, v, 2);
        m0[cc] = v * 0.25f;
    }
    if ((tk & 3) == 0) {
        const int l = lg * 8 + (tk >> 2);
        *(float4*)&g_m[(b * LL + l) * CC + cb] = make_float4(m0[0], m0[1], m0[2], m0[3]);
    }
}

// ---------------------------------------------------------------------------
// Kernel 3: R9 configuration (validated optimum: 64 regs, 4 blocks/SM).
// PDL consumer of k_col (g_m).
// ---------------------------------------------------------------------------
__global__ __launch_bounds__(256, 4)
void k_pair(const float* __restrict__ Wp, const float* __restrict__ bp,
            const float* __restrict__ png, const float* __restrict__ pnb,
            float* __restrict__ out)
{
    __shared__ __align__(16) float sm[LL * 36];
    __shared__ __align__(16) float su[8 * 512];
    __shared__ float snrm[LL];
    __shared__ float sbp[CPD], sg[CPD], sb[CPD];

    const int b  = blockIdx.x >> 3;
    const int ch = blockIdx.x & 7;
    const int tid = threadIdx.x;
    const int ib = ch * 8;

    // prologue: bias loads (independent of k_col output)
    if (tid < CPD) { sbp[tid] = bp[tid]; sg[tid] = png[tid]; sb[tid] = pnb[tid]; }

    cudaGridDependencySynchronize();

    for (int t = tid; t < LL * CC; t += 256)
        sm[(t >> 5) * 36 + (t & 31)] = g_m[b * (LL * CC) + t];
    __syncthreads();

    if (tid < LL) {
        float a = 0.f;
        #pragma unroll
        for (int c = 0; c < CC; c++) { float v = sm[tid * 36 + c]; a += v * v; }
        snrm[tid] = sqrtf(a);
    }

    // phase 1: u for 8 i's. thread -> (p0, c2) and (p0+8, c2).
    {
        const int p0 = tid >> 5;
        const int c2 = tid & 31;
        float a0[8], a1[8];
        #pragma unroll
        for (int il = 0; il < 8; il++) { a0[il] = 0.f; a1[il] = 0.f; }
        #pragma unroll 8
        for (int c1 = 0; c1 < CC; c1++) {
            const float w0 = Wp[p0 * 1024 + c1 * CC + c2];
            const float w1 = Wp[(p0 + 8) * 1024 + c1 * CC + c2];
            #pragma unroll
            for (int il = 0; il < 8; il++) {
                const float mv = sm[(ib + il) * 36 + c1];
                a0[il] += mv * w0;
                a1[il] += mv * w1;
            }
        }
        #pragma unroll
        for (int il = 0; il < 8; il++) {
            su[il * 512 + p0 * CC + c2]       = a0[il];
            su[il * 512 + (p0 + 8) * CC + c2] = a1[il];
        }
    }
    __syncthreads();

    // phase 2: thread = (il, jl); outputs (i, jl) and (i, jl+32) in parallel
    const int il = tid >> 5;
    const int jl = tid & 31;
    const int i  = ib + il;
    const int ja = jl, jb = jl + 32;

    float fa[CPD], fb[CPD];
    #pragma unroll
    for (int p = 0; p < CPD; p++) { fa[p] = 0.f; fb[p] = 0.f; }

    #pragma unroll
    for (int c4 = 0; c4 < 8; c4++) {
        const float4 ma = *(const float4*)&sm[ja * 36 + c4 * 4];
        const float4 mb = *(const float4*)&sm[jb * 36 + c4 * 4];
        #pragma unroll
        for (int p = 0; p < CPD; p++) {
            const float4 u4 = *(const float4*)&su[il * 512 + p * CC + c4 * 4];
            fa[p] += u4.x * ma.x + u4.y * ma.y + u4.z * ma.z + u4.w * ma.w;
            fb[p] += u4.x * mb.x + u4.y * mb.y + u4.z * mb.z + u4.w * mb.w;
        }
    }

    const float ni = snrm[i];
    const float inva = __fdividef(1.f, fmaxf(ni * snrm[ja], 1e-6f));
    const float invb = __fdividef(1.f, fmaxf(ni * snrm[jb], 1e-6f));

    float mua = 0.f, mub = 0.f;
    #pragma unroll
    for (int p = 0; p < CPD; p++) {
        fa[p] = fa[p] * inva + sbp[p];
        fb[p] = fb[p] * invb + sbp[p];
        mua += fa[p];
        mub += fb[p];
    }
    mua *= (1.f / CPD); mub *= (1.f / CPD);
    float va = 0.f, vb = 0.f;
    #pragma unroll
    for (int p = 0; p < CPD; p++) {
        float da = fa[p] - mua; va += da * da;
        float db = fb[p] - mub; vb += db * db;
    }
    const float rsa = rsqrtf(va * (1.f / CPD) + LN_EPS);
    const float rsb = rsqrtf(vb * (1.f / CPD) + LN_EPS);
    #pragma unroll
    for (int p = 0; p < CPD; p++) {
        const int obase = ((b * CPD + p) * LL + i) * LL;
        float xa = (fa[p] - mua) * rsa * sg[p] + sb[p];
        float xb = (fb[p] - mub) * rsb * sg[p] + sb[p];
        out[obase + ja] = silu(xa);
        out[obase + jb] = silu(xb);
    }
}

// ---------------------------------------------------------------------------
static inline void launch_pdl(void* func, dim3 grid, dim3 block, void** args)
{
    cudaLaunchConfig_t cfg = {};
    cfg.gridDim = grid;
    cfg.blockDim = block;
    cfg.dynamicSmemBytes = 0;
    cudaLaunchAttribute attr[1];
    attr[0].id = cudaLaunchAttributeProgrammaticStreamSerialization;
    attr[0].val.programmaticStreamSerializationAllowed = 1;
    cfg.attrs = attr;
    cfg.numAttrs = 1;
    cudaLaunchKernelExC(&cfg, func, args);
}

extern "C" void kernel_launch(void* const* d_in, const int* in_sizes, int n_in,
                              void* d_out, int out_size)
{
    const float* ctcf = (const float*)d_in[0];
    const float* hac  = (const float*)d_in[1];
    const float* me1  = (const float*)d_in[2];
    const float* me3  = (const float*)d_in[3];
    const float* ew   = (const float*)d_in[4];
    const float* eb   = (const float*)d_in[5];
    const float* pos  = (const float*)d_in[6];
    const float* riw  = (const float*)d_in[7];
    const float* rib  = (const float*)d_in[8];
    const float* row_ = (const float*)d_in[9];
    const float* rob  = (const float*)d_in[10];
    const float* rlg  = (const float*)d_in[11];
    const float* rlb  = (const float*)d_in[12];
    const float* ciw  = (const float*)d_in[13];
    const float* cib  = (const float*)d_in[14];
    const float* cow  = (const float*)d_in[15];
    const float* cob  = (const float*)d_in[16];
    const float* clg  = (const float*)d_in[17];
    const float* clb  = (const float*)d_in[18];
    const float* pw   = (const float*)d_in[19];
    const float* pb   = (const float*)d_in[20];
    const float* plg  = (const float*)d_in[21];
    const float* plb  = (const float*)d_in[22];
    float* out = (float*)d_out;

    k_pre<<<96, 64>>>(riw, rib, eb, pos, ew);

    {
        void* args[] = {(void*)&ctcf, (void*)&hac, (void*)&me1, (void*)&me3,
                        (void*)&ew, (void*)&eb, (void*)&pos,
                        (void*)&row_, (void*)&rob, (void*)&rlg, (void*)&rlb};
        launch_pdl((void*)k_row_attn, dim3(BB * SS * 2), dim3(256), args);
    }
    {
        void* args[] = {(void*)&ciw, (void*)&cib, (void*)&cow, (void*)&cob,
                        (void*)&clg, (void*)&clb};
        launch_pdl((void*)k_col_attn, dim3(BB * 8), dim3(256), args);
    }
    {
        void* args[] = {(void*)&pw, (void*)&pb, (void*)&plg, (void*)&plb,
                        (void*)&out};
        launch_pdl((void*)k_pair, dim3(BB * 8), dim3(256), args);
    }
}